// round 15
// baseline (speedup 1.0000x reference)
#include <cuda_runtime.h>
#include <math.h>

#define B 16
#define N 32
#define C 512
#define FEAT 224

#define HW0 784
#define HW1 196
#define HW2 49
#define OUT_ROW (C*(HW0+HW1+HW2))
#define OUT_OFF1 (C*HW0)         // 401408
#define OUT_OFF2 (C*(HW0+HW1))   // 501760

// ---------------- scratch (no allocations allowed) ----------------
__device__ float g_sum28p[B][2][HW0];  // per-8x8-tile sigmoid sum, split in 2 half-bands
__device__ float g_logits[3 * B * C];
__device__ float g_weights[3 * B * C];
__device__ int   g_cnt[3 * B];         // zero-init; reset by last block each run

// ---------------- K1: column-per-thread tile kernel, half-band split -----
// grid = (56, B), 224 threads (7 warps). Block (bq,b): band = bq/2,
// half = bq&1 covers 4 pixel rows. Thread t owns pixel column t: local
// column mask, 4-row loop with mask-change memoization, 8-lane segmented
// reduction, one atomicAdd per group into 28 tile sums (this half only).
__global__ void tile_kernel(const float* __restrict__ confs,
                            const float* __restrict__ boxes) {
    int bq = blockIdx.x;
    int band = bq >> 1, half = bq & 1;
    int b = blockIdx.y;
    int t = threadIdx.x;
    int lane = t & 31;

    __shared__ int sbx[N * 4];
    __shared__ float sconf[N];
    __shared__ unsigned rm4[4];
    __shared__ float stile[28];

    if (t < N * 4) sbx[t] = (int)floorf(boxes[b * N * 4 + t] * (float)FEAT);
    if (t < N) sconf[t] = confs[b * N + t];
    if (t < 28) stile[t] = 0.f;
    __syncthreads();

    // this half-band's 4 row masks
    if (t < 4) {
        int y = band * 8 + half * 4 + t;
        unsigned rm = 0;
#pragma unroll
        for (int n = 0; n < N; n++)
            rm |= (unsigned)(y >= sbx[4 * n + 1] && y < sbx[4 * n + 3]) << n;
        rm4[t] = rm;
    }

    // column mask for this thread's pixel column (broadcast LDS reads)
    unsigned cmask = 0;
#pragma unroll
    for (int n = 0; n < N; n++)
        cmask |= (unsigned)(t >= sbx[4 * n] && t < sbx[4 * n + 2]) << n;
    __syncthreads();

    float acc = 0.f;
    unsigned prev = 0xffffffffu;
    float sg = 0.f;
#pragma unroll
    for (int i = 0; i < 4; i++) {
        unsigned m = rm4[i] & cmask;
        if (m != prev) {
            float v = 0.f;
            unsigned mm = m;
            while (mm) {
                int j = __ffs(mm) - 1;
                v += sconf[j];
                mm &= mm - 1;
            }
            sg = __fdividef(1.f, 1.f + __expf(-v));
            prev = m;
        }
        acc += sg;
    }
    // segmented reduction: 8 consecutive lanes share one tile cell
    acc += __shfl_xor_sync(0xffffffffu, acc, 4);
    acc += __shfl_xor_sync(0xffffffffu, acc, 2);
    acc += __shfl_xor_sync(0xffffffffu, acc, 1);
    if ((lane & 7) == 0) atomicAdd(&stile[t >> 3], acc);
    __syncthreads();
    if (t < 28) g_sum28p[b][half][band * 28 + t] = stile[t];
}

// -------- K2: logits (2 channels/warp) + last-block softmax epilogue ------
// grid = (C/16, B, 3), 256 threads = 8 warps; each warp does 2 channels.
__global__ void logits_kernel(const float* __restrict__ f0,
                              const float* __restrict__ f1,
                              const float* __restrict__ f2) {
    int l = blockIdx.z, b = blockIdx.y;
    __shared__ __align__(16) float satt[HW0];

    int warp = threadIdx.x >> 5, lane = threadIdx.x & 31;
    int c0 = blockIdx.x * 16 + warp * 2;
    int t = threadIdx.x;
    float acc0 = 0.f, acc1 = 0.f;
    const float* gs = &g_sum28p[b][0][0];   // half 0
    const float* gh = gs + HW0;             // half 1

    if (l == 0) {
        for (int i = t; i < HW0; i += 256) satt[i] = (gs[i] + gh[i]) * (1.f / 64.f);
        __syncthreads();
        const float4* fp0 = (const float4*)(f0 + ((size_t)(b * C + c0)) * HW0);
        const float4* fp1 = fp0 + (HW0 / 4);
        const float4* ap = (const float4*)satt;
#pragma unroll
        for (int k = 0; k < 7; k++) {
            int i = lane + 32 * k;
            if (i < HW0 / 4) {
                float4 v0 = fp0[i], v1 = fp1[i], a = ap[i];
                acc0 = fmaf(v0.x, a.x, acc0);
                acc0 = fmaf(v0.y, a.y, acc0);
                acc0 = fmaf(v0.z, a.z, acc0);
                acc0 = fmaf(v0.w, a.w, acc0);
                acc1 = fmaf(v1.x, a.x, acc1);
                acc1 = fmaf(v1.y, a.y, acc1);
                acc1 = fmaf(v1.z, a.z, acc1);
                acc1 = fmaf(v1.w, a.w, acc1);
            }
        }
    } else if (l == 1) {
        if (t < HW1) {
            int ay = t / 14, ax = t % 14;
            int base = (2 * ay) * 28 + 2 * ax;
            float s = gs[base] + gs[base + 1] + gs[base + 28] + gs[base + 29]
                    + gh[base] + gh[base + 1] + gh[base + 28] + gh[base + 29];
            satt[t] = s * (1.f / 256.f);
        }
        __syncthreads();
        const float4* fp0 = (const float4*)(f1 + ((size_t)(b * C + c0)) * HW1);
        const float4* fp1 = fp0 + (HW1 / 4);
        const float4* ap = (const float4*)satt;
#pragma unroll
        for (int k = 0; k < 2; k++) {
            int i = lane + 32 * k;
            if (i < HW1 / 4) {
                float4 v0 = fp0[i], v1 = fp1[i], a = ap[i];
                acc0 = fmaf(v0.x, a.x, acc0);
                acc0 = fmaf(v0.y, a.y, acc0);
                acc0 = fmaf(v0.z, a.z, acc0);
                acc0 = fmaf(v0.w, a.w, acc0);
                acc1 = fmaf(v1.x, a.x, acc1);
                acc1 = fmaf(v1.y, a.y, acc1);
                acc1 = fmaf(v1.z, a.z, acc1);
                acc1 = fmaf(v1.w, a.w, acc1);
            }
        }
    } else {
        if (t < HW2) {
            int ay = t / 7, ax = t % 7;
            float s = 0.f;
#pragma unroll
            for (int iy = 0; iy < 4; iy++)
#pragma unroll
                for (int ix = 0; ix < 4; ix++) {
                    int idx = (4 * ay + iy) * 28 + 4 * ax + ix;
                    s += gs[idx] + gh[idx];
                }
            satt[t] = s * (1.f / 1024.f);
        }
        __syncthreads();
        const float* fp0 = f2 + ((size_t)(b * C + c0)) * HW2;
        const float* fp1 = fp0 + HW2;
#pragma unroll
        for (int k = 0; k < 2; k++) {
            int i = lane + 32 * k;
            if (i < HW2) {
                float a = satt[i];
                acc0 = fmaf(fp0[i], a, acc0);
                acc1 = fmaf(fp1[i], a, acc1);
            }
        }
    }

#pragma unroll
    for (int o = 16; o > 0; o >>= 1) {
        acc0 += __shfl_xor_sync(0xffffffffu, acc0, o);
        acc1 += __shfl_xor_sync(0xffffffffu, acc1, o);
    }
    int base = (l * B + b) * C;
    if (lane == 0) {
        g_logits[base + c0] = acc0;
        g_logits[base + c0 + 1] = acc1;
    }
    __syncthreads();

    // ---- last-block softmax epilogue ----
    __shared__ int is_last;
    if (t == 0) {
        __threadfence();
        is_last = (atomicAdd(&g_cnt[l * B + b], 1) == (C / 16) - 1);
    }
    __syncthreads();
    if (!is_last) return;
    if (t == 0) g_cnt[l * B + b] = 0;   // reset for next graph replay

    __shared__ float red[8];
    __shared__ float smax, ssum;
    float x0 = g_logits[base + t];
    float x1 = g_logits[base + t + 256];
    float m = fmaxf(x0, x1);
#pragma unroll
    for (int o = 16; o > 0; o >>= 1) m = fmaxf(m, __shfl_xor_sync(0xffffffffu, m, o));
    if (lane == 0) red[warp] = m;
    __syncthreads();
    if (t == 0) {
        float mm = red[0];
#pragma unroll
        for (int i = 1; i < 8; i++) mm = fmaxf(mm, red[i]);
        smax = mm;
    }
    __syncthreads();
    float e0 = __expf(x0 - smax), e1 = __expf(x1 - smax);
    float s = e0 + e1;
#pragma unroll
    for (int o = 16; o > 0; o >>= 1) s += __shfl_xor_sync(0xffffffffu, s, o);
    if (lane == 0) red[warp] = s;
    __syncthreads();
    if (t == 0) {
        float ss = 0.f;
#pragma unroll
        for (int i = 0; i < 8; i++) ss += red[i];
        ssum = ss;
    }
    __syncthreads();
    float inv = __fdividef(1.f, ssum);
    g_weights[base + t] = e0 * inv;
    g_weights[base + t + 256] = e1 * inv;
}

// ---------------- K3: pure streaming scale, warp-per-row -----------------
__global__ void scale_kernel(const float* __restrict__ f0,
                             const float* __restrict__ f1,
                             const float* __restrict__ f2,
                             float* __restrict__ out) {
    int l = blockIdx.y;
    int warp = threadIdx.x >> 5, lane = threadIdx.x & 31;
    int row = blockIdx.x * 16 + warp;   // 0 .. B*C-1
    int b = row >> 9, c = row & (C - 1);
    float w = __ldg(&g_weights[(l * B + b) * C + c]);

    if (l == 0) {
        const float4* src = (const float4*)(f0 + (size_t)row * HW0);
        float4* dst = (float4*)(out + (size_t)b * OUT_ROW + (size_t)c * HW0);
#pragma unroll
        for (int k = 0; k < 7; k++) {
            int i = lane + 32 * k;
            if (i < HW0 / 4) {
                float4 v = src[i];
                v.x *= w; v.y *= w; v.z *= w; v.w *= w;
                __stcs(&dst[i], v);
            }
        }
    } else if (l == 1) {
        const float4* src = (const float4*)(f1 + (size_t)row * HW1);
        float4* dst = (float4*)(out + (size_t)b * OUT_ROW + OUT_OFF1 + (size_t)c * HW1);
#pragma unroll
        for (int k = 0; k < 2; k++) {
            int i = lane + 32 * k;
            if (i < HW1 / 4) {
                float4 v = src[i];
                v.x *= w; v.y *= w; v.z *= w; v.w *= w;
                __stcs(&dst[i], v);
            }
        }
    } else {
        const float* src = f2 + (size_t)row * HW2;
        float* dst = out + (size_t)b * OUT_ROW + OUT_OFF2 + (size_t)c * HW2;
#pragma unroll
        for (int k = 0; k < 2; k++) {
            int i = lane + 32 * k;
            if (i < HW2) __stcs(&dst[i], src[i] * w);
        }
    }
}

extern "C" void kernel_launch(void* const* d_in, const int* in_sizes, int n_in,
                              void* d_out, int out_size) {
    const float* confs = (const float*)d_in[0];
    const float* boxes = (const float*)d_in[1];
    const float* f0 = (const float*)d_in[2];
    const float* f1 = (const float*)d_in[3];
    const float* f2 = (const float*)d_in[4];
    float* out = (float*)d_out;

    tile_kernel<<<dim3(56, B), 224>>>(confs, boxes);
    logits_kernel<<<dim3(C / 16, B, 3), 256>>>(f0, f1, f2);
    scale_kernel<<<dim3(B * C / 16, 3), 512>>>(f0, f1, f2, out);
}

// round 16
// speedup vs baseline: 1.0681x; 1.0681x over previous
#include <cuda_runtime.h>
#include <math.h>

#define B 16
#define N 32
#define C 512
#define FEAT 224

#define HW0 784
#define HW1 196
#define HW2 49
#define OUT_ROW (C*(HW0+HW1+HW2))
#define OUT_OFF1 (C*HW0)         // 401408
#define OUT_OFF2 (C*(HW0+HW1))   // 501760

// ---------------- scratch (no allocations allowed) ----------------
__device__ float g_sum28[B][HW0];   // per-8x8-tile sum of sigmoid
__device__ float g_logits[3 * B * C];
__device__ float g_weights[3 * B * C];
__device__ int   g_cnt[3 * B];      // zero-init; reset by last block each run

// ---------------- K1: column-per-thread tile kernel, SIMD masks ----------
// grid = (28 bands, B), 256 threads. Coordinates fit uint8; 4 boxes packed
// per word (byte i = box 4w+3-i) so the vcmp+nibble-pack trick yields bit
// k <-> box 4w+k. Thread t<224 owns pixel column t.
__global__ void tile_kernel(const float* __restrict__ confs,
                            const float* __restrict__ boxes) {
    int band = blockIdx.x, b = blockIdx.y;
    int t = threadIdx.x;
    int lane = t & 31;

    __shared__ int sbx[N * 4];
    __shared__ float sconf[N];
    __shared__ unsigned spx1[8], spx2[8], spy1[8], spy2[8];
    __shared__ unsigned rm8[8];
    __shared__ float stile[28];

    if (t < N * 4) sbx[t] = (int)floorf(boxes[b * N * 4 + t] * (float)FEAT);
    if (t < N) sconf[t] = confs[b * N + t];
    if (t < 28) stile[t] = 0.f;
    __syncthreads();

    // pack coordinate bytes: 32 threads, each one word
    if (t < 32) {
        int w = t & 7, coord = t >> 3;    // 0:x1 1:y1 2:x2 3:y2
        unsigned v = ((unsigned)sbx[4 * (4 * w + 3) + coord])
                   | ((unsigned)sbx[4 * (4 * w + 2) + coord] << 8)
                   | ((unsigned)sbx[4 * (4 * w + 1) + coord] << 16)
                   | ((unsigned)sbx[4 * (4 * w + 0) + coord] << 24);
        if (coord == 0) spx1[w] = v;
        else if (coord == 1) spy1[w] = v;
        else if (coord == 2) spx2[w] = v;
        else spy2[w] = v;
    }
    __syncthreads();

    // row masks for the band's 8 rows (8 threads, SIMD)
    if (t < 8) {
        unsigned yy = (unsigned)(band * 8 + t) * 0x01010101u;
        unsigned rm = 0;
#pragma unroll
        for (int w = 0; w < 8; w++) {
            unsigned m4 = __vcmpgeu4(yy, spy1[w]) & __vcmpltu4(yy, spy2[w]);
            rm |= (((m4 & 0x01010101u) * 0x08040201u) >> 24) << (4 * w);
        }
        rm8[t] = rm;
    }

    // column mask for this thread's column (SIMD, 8 words)
    unsigned cmask = 0;
    if (t < FEAT) {
        unsigned cc = (unsigned)t * 0x01010101u;
#pragma unroll
        for (int w = 0; w < 8; w++) {
            unsigned m4 = __vcmpgeu4(cc, spx1[w]) & __vcmpltu4(cc, spx2[w]);
            cmask |= (((m4 & 0x01010101u) * 0x08040201u) >> 24) << (4 * w);
        }
    }
    __syncthreads();

    if (t < FEAT) {
        float acc = 0.f;
        unsigned prev = 0xffffffffu;
        float sg = 0.f;
#pragma unroll
        for (int i = 0; i < 8; i++) {
            unsigned m = rm8[i] & cmask;
            if (m != prev) {
                float v = 0.f;
                unsigned mm = m;
                while (mm) {
                    int j = __ffs(mm) - 1;
                    v += sconf[j];
                    mm &= mm - 1;
                }
                sg = __fdividef(1.f, 1.f + __expf(-v));
                prev = m;
            }
            acc += sg;
        }
        // segmented reduction: 8 consecutive lanes share one tile cell
        acc += __shfl_xor_sync(0xffffffffu, acc, 4);
        acc += __shfl_xor_sync(0xffffffffu, acc, 2);
        acc += __shfl_xor_sync(0xffffffffu, acc, 1);
        if ((lane & 7) == 0) atomicAdd(&stile[t >> 3], acc);
    }
    __syncthreads();
    if (t < 28) g_sum28[b][band * 28 + t] = stile[t];
}

// -------- K2: logits (2 channels/warp) + last-block softmax epilogue ------
// grid = (C/16, B, 3), 256 threads = 8 warps; each warp does 2 channels.
__global__ void logits_kernel(const float* __restrict__ f0,
                              const float* __restrict__ f1,
                              const float* __restrict__ f2) {
    int l = blockIdx.z, b = blockIdx.y;
    __shared__ __align__(16) float satt[HW0];

    int warp = threadIdx.x >> 5, lane = threadIdx.x & 31;
    int c0 = blockIdx.x * 16 + warp * 2;
    int t = threadIdx.x;
    float acc0 = 0.f, acc1 = 0.f;
    const float* gs = g_sum28[b];

    if (l == 0) {
        for (int i = t; i < HW0; i += 256) satt[i] = gs[i] * (1.f / 64.f);
        __syncthreads();
        const float4* fp0 = (const float4*)(f0 + ((size_t)(b * C + c0)) * HW0);
        const float4* fp1 = fp0 + (HW0 / 4);
        const float4* ap = (const float4*)satt;
#pragma unroll
        for (int k = 0; k < 7; k++) {
            int i = lane + 32 * k;
            if (i < HW0 / 4) {
                float4 v0 = fp0[i], v1 = fp1[i], a = ap[i];
                acc0 = fmaf(v0.x, a.x, acc0);
                acc0 = fmaf(v0.y, a.y, acc0);
                acc0 = fmaf(v0.z, a.z, acc0);
                acc0 = fmaf(v0.w, a.w, acc0);
                acc1 = fmaf(v1.x, a.x, acc1);
                acc1 = fmaf(v1.y, a.y, acc1);
                acc1 = fmaf(v1.z, a.z, acc1);
                acc1 = fmaf(v1.w, a.w, acc1);
            }
        }
    } else if (l == 1) {
        if (t < HW1) {
            int ay = t / 14, ax = t % 14;
            int base = (2 * ay) * 28 + 2 * ax;
            float s = gs[base] + gs[base + 1] + gs[base + 28] + gs[base + 29];
            satt[t] = s * (1.f / 256.f);
        }
        __syncthreads();
        const float4* fp0 = (const float4*)(f1 + ((size_t)(b * C + c0)) * HW1);
        const float4* fp1 = fp0 + (HW1 / 4);
        const float4* ap = (const float4*)satt;
#pragma unroll
        for (int k = 0; k < 2; k++) {
            int i = lane + 32 * k;
            if (i < HW1 / 4) {
                float4 v0 = fp0[i], v1 = fp1[i], a = ap[i];
                acc0 = fmaf(v0.x, a.x, acc0);
                acc0 = fmaf(v0.y, a.y, acc0);
                acc0 = fmaf(v0.z, a.z, acc0);
                acc0 = fmaf(v0.w, a.w, acc0);
                acc1 = fmaf(v1.x, a.x, acc1);
                acc1 = fmaf(v1.y, a.y, acc1);
                acc1 = fmaf(v1.z, a.z, acc1);
                acc1 = fmaf(v1.w, a.w, acc1);
            }
        }
    } else {
        if (t < HW2) {
            int ay = t / 7, ax = t % 7;
            float s = 0.f;
#pragma unroll
            for (int iy = 0; iy < 4; iy++)
#pragma unroll
                for (int ix = 0; ix < 4; ix++)
                    s += gs[(4 * ay + iy) * 28 + 4 * ax + ix];
            satt[t] = s * (1.f / 1024.f);
        }
        __syncthreads();
        const float* fp0 = f2 + ((size_t)(b * C + c0)) * HW2;
        const float* fp1 = fp0 + HW2;
#pragma unroll
        for (int k = 0; k < 2; k++) {
            int i = lane + 32 * k;
            if (i < HW2) {
                float a = satt[i];
                acc0 = fmaf(fp0[i], a, acc0);
                acc1 = fmaf(fp1[i], a, acc1);
            }
        }
    }

#pragma unroll
    for (int o = 16; o > 0; o >>= 1) {
        acc0 += __shfl_xor_sync(0xffffffffu, acc0, o);
        acc1 += __shfl_xor_sync(0xffffffffu, acc1, o);
    }
    int base = (l * B + b) * C;
    if (lane == 0) {
        g_logits[base + c0] = acc0;
        g_logits[base + c0 + 1] = acc1;
    }
    __syncthreads();

    // ---- last-block softmax epilogue ----
    __shared__ int is_last;
    if (t == 0) {
        __threadfence();
        is_last = (atomicAdd(&g_cnt[l * B + b], 1) == (C / 16) - 1);
    }
    __syncthreads();
    if (!is_last) return;
    if (t == 0) g_cnt[l * B + b] = 0;   // reset for next graph replay

    __shared__ float red[8];
    __shared__ float smax, ssum;
    float x0 = g_logits[base + t];
    float x1 = g_logits[base + t + 256];
    float m = fmaxf(x0, x1);
#pragma unroll
    for (int o = 16; o > 0; o >>= 1) m = fmaxf(m, __shfl_xor_sync(0xffffffffu, m, o));
    if (lane == 0) red[warp] = m;
    __syncthreads();
    if (t == 0) {
        float mm = red[0];
#pragma unroll
        for (int i = 1; i < 8; i++) mm = fmaxf(mm, red[i]);
        smax = mm;
    }
    __syncthreads();
    float e0 = __expf(x0 - smax), e1 = __expf(x1 - smax);
    float s = e0 + e1;
#pragma unroll
    for (int o = 16; o > 0; o >>= 1) s += __shfl_xor_sync(0xffffffffu, s, o);
    if (lane == 0) red[warp] = s;
    __syncthreads();
    if (t == 0) {
        float ss = 0.f;
#pragma unroll
        for (int i = 0; i < 8; i++) ss += red[i];
        ssum = ss;
    }
    __syncthreads();
    float inv = __fdividef(1.f, ssum);
    g_weights[base + t] = e0 * inv;
    g_weights[base + t + 256] = e1 * inv;
}

// ---------------- K3: pure streaming scale, warp-per-row -----------------
__global__ void scale_kernel(const float* __restrict__ f0,
                             const float* __restrict__ f1,
                             const float* __restrict__ f2,
                             float* __restrict__ out) {
    int l = blockIdx.y;
    int warp = threadIdx.x >> 5, lane = threadIdx.x & 31;
    int row = blockIdx.x * 16 + warp;   // 0 .. B*C-1
    int b = row >> 9, c = row & (C - 1);
    float w = __ldg(&g_weights[(l * B + b) * C + c]);

    if (l == 0) {
        const float4* src = (const float4*)(f0 + (size_t)row * HW0);
        float4* dst = (float4*)(out + (size_t)b * OUT_ROW + (size_t)c * HW0);
#pragma unroll
        for (int k = 0; k < 7; k++) {
            int i = lane + 32 * k;
            if (i < HW0 / 4) {
                float4 v = src[i];
                v.x *= w; v.y *= w; v.z *= w; v.w *= w;
                __stcs(&dst[i], v);
            }
        }
    } else if (l == 1) {
        const float4* src = (const float4*)(f1 + (size_t)row * HW1);
        float4* dst = (float4*)(out + (size_t)b * OUT_ROW + OUT_OFF1 + (size_t)c * HW1);
#pragma unroll
        for (int k = 0; k < 2; k++) {
            int i = lane + 32 * k;
            if (i < HW1 / 4) {
                float4 v = src[i];
                v.x *= w; v.y *= w; v.z *= w; v.w *= w;
                __stcs(&dst[i], v);
            }
        }
    } else {
        const float* src = f2 + (size_t)row * HW2;
        float* dst = out + (size_t)b * OUT_ROW + OUT_OFF2 + (size_t)c * HW2;
#pragma unroll
        for (int k = 0; k < 2; k++) {
            int i = lane + 32 * k;
            if (i < HW2) __stcs(&dst[i], src[i] * w);
        }
    }
}

extern "C" void kernel_launch(void* const* d_in, const int* in_sizes, int n_in,
                              void* d_out, int out_size) {
    const float* confs = (const float*)d_in[0];
    const float* boxes = (const float*)d_in[1];
    const float* f0 = (const float*)d_in[2];
    const float* f1 = (const float*)d_in[3];
    const float* f2 = (const float*)d_in[4];
    float* out = (float*)d_out;

    tile_kernel<<<dim3(28, B), 256>>>(confs, boxes);
    logits_kernel<<<dim3(C / 16, B, 3), 256>>>(f0, f1, f2);
    scale_kernel<<<dim3(B * C / 16, 3), 512>>>(f0, f1, f2, out);
}